// round 10
// baseline (speedup 1.0000x reference)
#include <cuda_runtime.h>
#include <cstdint>
#include <math.h>

#define SEQ   2048
#define BATCH 64
#define INP   256
#define HID   256

typedef unsigned long long ull;

// ---------- packed f32x2 helpers (Blackwell FFMA2 path, PTX-only) ----------
__device__ __forceinline__ void ffma2(ull& d, ull a, ull b) {
    asm("fma.rn.f32x2 %0, %1, %2, %0;" : "+l"(d) : "l"(a), "l"(b));
}
__device__ __forceinline__ ull pk(float a, float b) {
    ull r; asm("mov.b64 %0, {%1, %2};" : "=l"(r) : "f"(a), "f"(b)); return r;
}
__device__ __forceinline__ ull pku(unsigned a, unsigned b) {
    ull r; asm("mov.b64 %0, {%1, %2};" : "=l"(r) : "r"(a), "r"(b)); return r;
}
__device__ __forceinline__ float2 unpk(ull v) {
    float x, y; asm("mov.b64 {%0, %1}, %2;" : "=f"(x), "=f"(y) : "l"(v));
    return make_float2(x, y);
}
__device__ __forceinline__ unsigned smem_u32(const void* p) {
    unsigned a;
    asm("{ .reg .u64 t; cvta.to.shared.u64 t, %1; cvt.u32.u64 %0, t; }"
        : "=r"(a) : "l"(p));
    return a;
}
__device__ __forceinline__ unsigned mapa_peer(unsigned local_addr, unsigned peer) {
    unsigned r;
    asm("mapa.shared::cluster.u32 %0, %1, %2;" : "=r"(r) : "r"(local_addr), "r"(peer));
    return r;
}
// Branch-free tanh: 1 - 2/(e^{2x}+1). ex2/rcp approx, abs err ~1e-7.
__device__ __forceinline__ float fast_tanh(float x) {
    float e;
    asm("ex2.approx.ftz.f32 %0, %1;" : "=f"(e) : "f"(x * 2.8853900817779268f));
    float r;
    asm("rcp.approx.ftz.f32 %0, %1;" : "=f"(r) : "f"(e + 1.0f));
    return fmaf(-2.0f, r, 1.0f);
}

// =====================================================================
// Phase 1: xp[t,b,h] = x[t,b]·W_ih[h] + b_ih[h] + b_hh[h]  (unchanged)
// =====================================================================
__global__ __launch_bounds__(256) void xp_gemm_kernel(
    const float* __restrict__ x,
    const float* __restrict__ Wih,
    const float* __restrict__ bih,
    const float* __restrict__ bhh,
    float* __restrict__ out)
{
    __shared__ float Xs[32][68];
    __shared__ float Ws[32][257];

    const int t   = blockIdx.x;
    const int tid = threadIdx.x;
    const int tn  = tid & 31;
    const int tm  = tid >> 5;
    const int m0  = tm * 8;

    const float* xt = x + (size_t)t * BATCH * INP;

    ull acc[8][4];
    #pragma unroll
    for (int u = 0; u < 8; ++u)
        #pragma unroll
        for (int v = 0; v < 4; ++v) acc[u][v] = 0ull;

    for (int kc = 0; kc < INP; kc += 32) {
        #pragma unroll
        for (int r = 0; r < 2; ++r) {
            int idx = tid + 256 * r;
            int m   = idx >> 3;
            int k4  = (idx & 7) * 4;
            float4 v = *(const float4*)(xt + (size_t)m * INP + kc + k4);
            Xs[k4 + 0][m] = v.x; Xs[k4 + 1][m] = v.y;
            Xs[k4 + 2][m] = v.z; Xs[k4 + 3][m] = v.w;
        }
        #pragma unroll
        for (int r = 0; r < 8; ++r) {
            int idx = tid + 256 * r;
            int h   = idx >> 3;
            int k4  = (idx & 7) * 4;
            float4 v = *(const float4*)(Wih + (size_t)h * INP + kc + k4);
            Ws[k4 + 0][h] = v.x; Ws[k4 + 1][h] = v.y;
            Ws[k4 + 2][h] = v.z; Ws[k4 + 3][h] = v.w;
        }
        __syncthreads();

        #pragma unroll
        for (int k = 0; k < 32; ++k) {
            float4 a0 = *(const float4*)&Xs[k][m0];
            float4 a1 = *(const float4*)&Xs[k][m0 + 4];
            ull ap[8];
            ap[0] = pk(a0.x, a0.x); ap[1] = pk(a0.y, a0.y);
            ap[2] = pk(a0.z, a0.z); ap[3] = pk(a0.w, a0.w);
            ap[4] = pk(a1.x, a1.x); ap[5] = pk(a1.y, a1.y);
            ap[6] = pk(a1.z, a1.z); ap[7] = pk(a1.w, a1.w);

            float w[8];
            #pragma unroll
            for (int v = 0; v < 8; ++v) w[v] = Ws[k][tn + 32 * v];

            #pragma unroll
            for (int v2 = 0; v2 < 4; ++v2) {
                ull wp = pk(w[2 * v2], w[2 * v2 + 1]);
                #pragma unroll
                for (int u = 0; u < 8; ++u)
                    ffma2(acc[u][v2], wp, ap[u]);
            }
        }
        __syncthreads();
    }

    float ba[4], bb[4];
    #pragma unroll
    for (int v2 = 0; v2 < 4; ++v2) {
        int hA = tn + 64 * v2, hB = hA + 32;
        ba[v2] = bih[hA] + bhh[hA];
        bb[v2] = bih[hB] + bhh[hB];
    }
    float* ot = out + (size_t)t * BATCH * HID;
    #pragma unroll
    for (int u = 0; u < 8; ++u) {
        float* row = ot + (size_t)(m0 + u) * HID;
        #pragma unroll
        for (int v2 = 0; v2 < 4; ++v2) {
            float2 s = unpk(acc[u][v2]);
            row[tn + 64 * v2]      = s.x + ba[v2];
            row[tn + 64 * v2 + 32] = s.y + bb[v2];
        }
    }
}

// =====================================================================
// Phase 2: serial scan, v8 — warp-internal k-split, shfl combine.
// Cluster {2b,2b+1}; rank r finalizes rows [128r,+128) over all 256 k.
// 512 threads, warp w: rows 8w..8w+7; lane l: jj = 8w+(l>>2), g = l&3.
//   window g: g0,g1 = local k ([128r,+64),[128r+64,+64)),
//             g2,g3 = peer  k.
// ALL h stored as {f32,seq} u64 pairs in one array:
//   pairs[parity][window*66 + slot]  (66-ull window stride -> the 4
//   per-instruction addresses land in distinct banks; parity stride
//   264 ull). Local windows (0,1) ordered by the per-step bar.sync;
//   remote windows (2,3) self-validated by seq (collective poll,
//   4 slots/lane). Row partials combine via 2x shfl_xor (no smem hop).
//   g==0 lanes store: local pair, remote pair (st.shared::cluster.u64,
//   single-copy atomic), STG. No fences, no mbarriers.
// =====================================================================
#define WSTR  66                 // window stride in ull
#define PSTR  (4 * WSTR)         // parity stride in ull (264)

__global__ __launch_bounds__(512, 1) __cluster_dims__(2, 1, 1)
void rnn_scan_kernel(
    const float* __restrict__ Whh,  // [HID][HID]
    float* __restrict__ out)        // in: xp, out: h   [SEQ][BATCH][HID]
{
    __shared__ alignas(16) ull pairs[2 * PSTR];   // 4224 B

    const int bidx = blockIdx.x;
    const int b    = bidx >> 1;
    const int r    = bidx & 1;             // cluster rank
    const int tid  = threadIdx.x;
    const int l    = tid & 31;
    const int w    = tid >> 5;
    const int jj   = 8 * w + (l >> 2);     // my row within half
    const int g    = l & 3;                // k-window
    const int j    = 128 * r + jj;         // global row

    const int koff = (g < 2) ? (128 * r + 64 * g)
                             : (128 * (1 - r) + 64 * (g - 2));

    // ---- register-resident W: W_hh[j][koff + 0..63] ----
    ull wreg[32];
    {
        const float* wrow = Whh + (size_t)j * HID + koff;
        #pragma unroll
        for (int p = 0; p < 32; ++p)
            wreg[p] = *(const ull*)(wrow + 2 * p);
    }

    // ---- init: both parities {val=0, seq=0} ----
    for (int i = tid; i < 2 * PSTR; i += 512) pairs[i] = 0ull;
    __syncthreads();
    asm volatile("barrier.cluster.arrive.aligned;" ::: "memory");
    asm volatile("barrier.cluster.wait.aligned;"   ::: "memory");

    const unsigned peer      = (unsigned)(r ^ 1);
    const unsigned pair_l    = smem_u32(pairs);
    const unsigned peer_pair = mapa_peer(pair_l, peer);

    // my row's publish slots (window 0/1 local; window 2/3 on peer)
    const unsigned lslot = (unsigned)((jj < 64) ? jj : (WSTR + jj - 64)) * 8u;
    const unsigned rslot = (unsigned)((jj < 64) ? (2 * WSTR + jj)
                                                : (3 * WSTR + jj - 64)) * 8u;

    const size_t stride = (size_t)BATCH * HID;
    float* col = out + (size_t)b * HID + j;

    // xp queue, depth 2 (all 4 lanes of a row load the same address)
    float xq0 = __ldcg(col);
    float xq1 = __ldcg(col + stride);

    for (int t = 0; t < SEQ; ++t) {
        const unsigned sp = (unsigned)(t & 1);   // publish parity
        const unsigned rp = sp ^ 1u;             // read parity

        // ---- collective poll of the 128 remote slots (4 per lane) ----
        {
            const unsigned base = pair_l + rp * (PSTR * 8u);
            const unsigned aA = base + (2 * WSTR + l) * 8u;
            const unsigned aB = aA + 32u * 8u;
            const unsigned aC = base + (3 * WSTR + l) * 8u;
            const unsigned aD = aC + 32u * 8u;
            const unsigned T  = (unsigned)t;
            unsigned ok;
            do {
                ull v0, v1, v2, v3;
                asm volatile("ld.volatile.shared.u64 %0, [%1];"
                             : "=l"(v0) : "r"(aA) : "memory");
                asm volatile("ld.volatile.shared.u64 %0, [%1];"
                             : "=l"(v1) : "r"(aB) : "memory");
                asm volatile("ld.volatile.shared.u64 %0, [%1];"
                             : "=l"(v2) : "r"(aC) : "memory");
                asm volatile("ld.volatile.shared.u64 %0, [%1];"
                             : "=l"(v3) : "r"(aD) : "memory");
                ok = ((unsigned)(v0 >> 32) == T) & ((unsigned)(v1 >> 32) == T)
                   & ((unsigned)(v2 >> 32) == T) & ((unsigned)(v3 >> 32) == T);
            } while (__all_sync(0xFFFFFFFFu, ok) == 0);
        }

        // ---- matvec over my window: 32 x LDS.128 (2 pairs each) ----
        const uint4* pq = (const uint4*)((const char*)pairs
                           + rp * (PSTR * 8) + g * (WSTR * 8));
        ull a0 = 0ull, a1 = 0ull, a2 = 0ull, a3 = 0ull;
        #pragma unroll
        for (int q = 0; q < 32; q += 4) {
            uint4 v0 = pq[q + 0];
            uint4 v1 = pq[q + 1];
            uint4 v2 = pq[q + 2];
            uint4 v3 = pq[q + 3];
            ffma2(a0, wreg[q + 0], pku(v0.x, v0.z));
            ffma2(a1, wreg[q + 1], pku(v1.x, v1.z));
            ffma2(a2, wreg[q + 2], pku(v2.x, v2.z));
            ffma2(a3, wreg[q + 3], pku(v3.x, v3.z));
        }
        float2 s0 = unpk(a0), s1 = unpk(a1), s2 = unpk(a2), s3 = unpk(a3);
        float part = ((s0.x + s0.y) + (s1.x + s1.y))
                   + ((s2.x + s2.y) + (s3.x + s3.y));

        // ---- combine the 4 window partials within the lane quad ----
        part += __shfl_xor_sync(0xFFFFFFFFu, part, 1);
        part += __shfl_xor_sync(0xFFFFFFFFu, part, 2);

        // all 4 lanes compute val branchlessly; only g==0 stores
        float val = fast_tanh(xq0 + part);

        if (g == 0) {
            ull hv = pku(__float_as_uint(val), (unsigned)(t + 1));
            // local pair (ordered by the bar.sync below)
            asm volatile("st.shared.u64 [%0], %1;"
                         :: "r"(pair_l + sp * (PSTR * 8u) + lslot),
                            "l"(hv) : "memory");
            // remote pair (single-copy-atomic u64; seq validates payload)
            if (t + 1 < SEQ) {
                asm volatile("st.shared::cluster.u64 [%0], %1;"
                             :: "r"(peer_pair + sp * (PSTR * 8u) + rslot),
                                "l"(hv) : "memory");
            }
            col[(size_t)t * stride] = val;   // h_t -> gmem
        }

        // advance xp queue (all lanes; same address per quad -> broadcast)
        xq0 = xq1;
        if (t + 2 < SEQ) xq1 = __ldcg(col + (size_t)(t + 2) * stride);

        __syncthreads();   // orders local pair stores; one BAR per step
    }

    asm volatile("barrier.cluster.arrive.aligned;" ::: "memory");
    asm volatile("barrier.cluster.wait.aligned;"   ::: "memory");
}

// =====================================================================
extern "C" void kernel_launch(void* const* d_in, const int* in_sizes, int n_in,
                              void* d_out, int out_size) {
    const float* x   = (const float*)d_in[0];  // [SEQ][BATCH][INP]
    const float* Wih = (const float*)d_in[1];  // [HID][INP]
    const float* Whh = (const float*)d_in[2];  // [HID][HID]
    const float* bih = (const float*)d_in[3];  // [HID]
    const float* bhh = (const float*)d_in[4];  // [HID]
    float* out = (float*)d_out;                // [SEQ][BATCH][HID]

    xp_gemm_kernel<<<SEQ, 256>>>(x, Wih, bih, bhh, out);
    rnn_scan_kernel<<<2 * BATCH, 512>>>(Whh, out);
}